// round 15
// baseline (speedup 1.0000x reference)
#include <cuda_runtime.h>

#define N_NODES 100000
#define N_EDGES 1600000

// Scratch (__device__ globals; zero-initialized at load; k_nodemid re-zeroes
// g_deg/g_agg after consuming them, so the invariant holds for every call)
__device__ float  g_deg[N_NODES];
__device__ float  g_dis[N_NODES];
__device__ float2 g_y[N_NODES];        // y[n] = dis[n] * x[n]
__device__ float2 g_agg[N_NODES];      // layer-1 raw scatter target
__device__ float  g_t[N_NODES];        // t[n] = dis[n] * s[n]

// v2 float reduction (one L2 sector instead of two)
__device__ __forceinline__ void red_add_v2(float2* addr, float a, float b) {
    asm volatile("red.global.add.v2.f32 [%0], {%1, %2};"
                 :: "l"(addr), "f"(a), "f"(b) : "memory");
}

// ---------------------------------------------------------------------------
// K1: degree of target nodes (4 edges/thread, int4 stream). First kernel —
// launched normally.
__global__ void __launch_bounds__(256) k_deg(const int4* __restrict__ col4) {
    int i = blockIdx.x * blockDim.x + threadIdx.x;
    if (i < N_EDGES / 4) {
        int4 c = col4[i];
        atomicAdd(&g_deg[c.x], 1.0f);
        atomicAdd(&g_deg[c.y], 1.0f);
        atomicAdd(&g_deg[c.z], 1.0f);
        atomicAdd(&g_deg[c.w], 1.0f);
    }
}

// K2: dis = deg^-1/2; y[n] = dis[n]*x[n]; zero out[].
// PDL: x is a harness input -> load before gridsync (overlaps k_deg tail).
__global__ void __launch_bounds__(256) k_dis(const float* __restrict__ x,
                                             float* __restrict__ out) {
    int n = blockIdx.x * blockDim.x + threadIdx.x;
    float2 xv = make_float2(0.0f, 0.0f);
    if (n < N_NODES) xv = ((const float2*)x)[n];   // input-only prefetch
    cudaGridDependencySynchronize();               // wait: k_deg complete
    if (n < N_NODES) {
        float d   = g_deg[n];
        float dis = (d > 0.0f) ? rsqrtf(d) : 0.0f;
        g_dis[n]  = dis;
        g_y[n]    = make_float2(dis * xv.x, dis * xv.y);
        out[n]    = 0.0f;
    }
}

// K3: layer-1 edge scatter: agg_raw[c] += y[r].
// PDL: edge-index stream is input-only -> loads overlap k_dis.
__global__ void __launch_bounds__(256) k_edge1(const int4* __restrict__ row4,
                                               const int4* __restrict__ col4) {
    int i = blockIdx.x * blockDim.x + threadIdx.x;
    int4 r = make_int4(0, 0, 0, 0), c = make_int4(0, 0, 0, 0);
    bool act = i < N_EDGES / 4;
    if (act) { r = row4[i]; c = col4[i]; }         // input-only prefetch
    cudaGridDependencySynchronize();               // wait: k_dis complete
    if (act) {
        float2 y0 = g_y[r.x];
        float2 y1 = g_y[r.y];
        float2 y2 = g_y[r.z];
        float2 y3 = g_y[r.w];
        red_add_v2(&g_agg[c.x], y0.x, y0.y);
        red_add_v2(&g_agg[c.y], y1.x, y1.y);
        red_add_v2(&g_agg[c.z], y2.x, y2.y);
        red_add_v2(&g_agg[c.w], y3.x, y3.y);
    }
}

// K4: per-node MLP middle — 2 adjacent nodes/thread, 64-thread blocks
// (782 blocks/148 SMs: smooth placement; 391x128 had a ±38% tail tax).
// Also re-zeroes g_agg/g_deg here (mid-pipeline, hidden) instead of k_final.
// PDL: weight loads (inputs) into smem happen before gridsync.
__global__ void __launch_bounds__(64) k_nodemid(const float* __restrict__ W1,
                                                const float* __restrict__ b1,
                                                const float* __restrict__ W2) {
    __shared__ float4 s_w[64];   // (W1a, W1b, b1, W2) per feature
    int t = threadIdx.x;
    int g = blockIdx.x * blockDim.x + t;   // pair index: nodes 2g, 2g+1
    int n0 = 2 * g;

    s_w[t] = make_float4(W1[t], W1[64 + t], b1[t], W2[t]);  // input-only
    cudaGridDependencySynchronize();               // wait: k_edge1 complete

    float2 dis2 = make_float2(0.0f, 0.0f);
    float4 ar2  = make_float4(0.0f, 0.0f, 0.0f, 0.0f);
    if (n0 < N_NODES) {
        dis2 = ((const float2*)g_dis)[g];     // dis[2g], dis[2g+1]
        ar2  = ((const float4*)g_agg)[g];     // agg[2g].xy, agg[2g+1].xy
        // re-zero scratch for the next call (coalesced, off the critical tail)
        ((float4*)g_agg)[g] = make_float4(0.0f, 0.0f, 0.0f, 0.0f);
        ((float2*)g_deg)[g] = make_float2(0.0f, 0.0f);
    }
    __syncthreads();

    if (n0 < N_NODES) {
        float a0 = dis2.x * ar2.x, a1 = dis2.x * ar2.y;   // node 2g
        float c0 = dis2.y * ar2.z, c1 = dis2.y * ar2.w;   // node 2g+1
        float sa0 = 0.0f, sa1 = 0.0f, sb0 = 0.0f, sb1 = 0.0f;
#pragma unroll
        for (int f = 0; f < 64; f += 2) {
            float4 w0 = s_w[f + 0];
            float4 w1 = s_w[f + 1];
            float ha0 = fmaf(a1, w0.y, fmaf(a0, w0.x, w0.z));
            float hb0 = fmaf(c1, w0.y, fmaf(c0, w0.x, w0.z));
            float ha1 = fmaf(a1, w1.y, fmaf(a0, w1.x, w1.z));
            float hb1 = fmaf(c1, w1.y, fmaf(c0, w1.x, w1.z));
            sa0 = fmaf(fmaxf(ha0, 0.0f), w0.w, sa0);
            sb0 = fmaf(fmaxf(hb0, 0.0f), w0.w, sb0);
            sa1 = fmaf(fmaxf(ha1, 0.0f), w1.w, sa1);
            sb1 = fmaf(fmaxf(hb1, 0.0f), w1.w, sb1);
        }
        float2 res = make_float2(dis2.x * (sa0 + sa1), dis2.y * (sb0 + sb1));
        ((float2*)g_t)[g] = res;
    }
}

// K5: layer-2 edge scatter: out_raw[c] += t[r].
__global__ void __launch_bounds__(256) k_edge2(const int4* __restrict__ row4,
                                               const int4* __restrict__ col4,
                                               float* __restrict__ out) {
    int i = blockIdx.x * blockDim.x + threadIdx.x;
    int4 r = make_int4(0, 0, 0, 0), c = make_int4(0, 0, 0, 0);
    bool act = i < N_EDGES / 4;
    if (act) { r = row4[i]; c = col4[i]; }         // input-only prefetch
    cudaGridDependencySynchronize();               // wait: k_nodemid complete
    if (act) {
        float t0 = g_t[r.x];
        float t1 = g_t[r.y];
        float t2 = g_t[r.z];
        float t3 = g_t[r.w];
        atomicAdd(&out[c.x], t0);
        atomicAdd(&out[c.y], t1);
        atomicAdd(&out[c.z], t2);
        atomicAdd(&out[c.w], t3);
    }
}

// K6: out = relu(dis[n]*out_raw + b2)  (lean final kernel — no scratch zeroing)
__global__ void __launch_bounds__(256) k_final(float* __restrict__ out,
                                               const float* __restrict__ b2) {
    int n = blockIdx.x * blockDim.x + threadIdx.x;
    float bias = b2[0];                            // input-only prefetch
    cudaGridDependencySynchronize();               // wait: k_edge2 complete
    if (n < N_NODES) {
        out[n] = fmaxf(fmaf(g_dis[n], out[n], bias), 0.0f);
    }
}

// ---------------------------------------------------------------------------
// PDL launch helper: launch with ProgrammaticStreamSerialization so the kernel
// may start while its stream predecessor is still running; correctness comes
// from cudaGridDependencySynchronize() inside each kernel.
template <typename... Args>
static void launch_pss(void (*kern)(Args...), int grid, int block, Args... args) {
    cudaLaunchConfig_t cfg = {};
    cfg.gridDim  = dim3(grid, 1, 1);
    cfg.blockDim = dim3(block, 1, 1);
    cfg.dynamicSmemBytes = 0;
    cfg.stream = 0;
    cudaLaunchAttribute attr[1];
    attr[0].id = cudaLaunchAttributeProgrammaticStreamSerialization;
    attr[0].val.programmaticStreamSerializationAllowed = 1;
    cfg.attrs = attr;
    cfg.numAttrs = 1;
    cudaLaunchKernelEx(&cfg, kern, args...);
}

extern "C" void kernel_launch(void* const* d_in, const int* in_sizes, int n_in,
                              void* d_out, int out_size) {
    const float* x  = (const float*)d_in[0];   // [N,2] f32
    const int*   ei = (const int*)d_in[1];     // [2,E] int32 (JAX x64 off)
    const float* W1 = (const float*)d_in[2];   // [2,64]
    const float* b1 = (const float*)d_in[3];   // [64]
    const float* W2 = (const float*)d_in[4];   // [64,1]
    const float* b2 = (const float*)d_in[5];   // [1]
    float*       out = (float*)d_out;          // [N,1]

    const int4* row4 = (const int4*)ei;               // source
    const int4* col4 = (const int4*)(ei + N_EDGES);   // target

    const int BT = 256;
    const int nodeBlocks  = (N_NODES + BT - 1) / BT;
    const int edgeBlocks4 = (N_EDGES / 4 + BT - 1) / BT;
    const int pairBlocks  = (N_NODES / 2 + 63) / 64;     // 2 nodes/thread, BT=64

    k_deg<<<edgeBlocks4, BT>>>(col4);                       // first: normal
    launch_pss(k_dis,     nodeBlocks,  BT,  x, out);
    launch_pss(k_edge1,   edgeBlocks4, BT,  row4, col4);
    launch_pss(k_nodemid, pairBlocks,  64,  W1, b1, W2);
    launch_pss(k_edge2,   edgeBlocks4, BT,  row4, col4, out);
    launch_pss(k_final,   nodeBlocks,  BT,  out, b2);
}